// round 13
// baseline (speedup 1.0000x reference)
#include <cuda_runtime.h>
#include <cuda_bf16.h>
#include <math.h>
#include <cstdint>

// RotationalConv2D v13 — GB300 sm_103a
// A: per-patch angle + 25 tap records (weights float4 + byte-offset uint4),
//    j-major tables (L2-resident); block 0 also stages tf32 B fragments.
// B: record-driven main kernel: 6 LDG + 16 FMA + 4 cvt per (u,j); zero
//    coordinate math. tf32 mma.sync GEMM as v11.

#define HDIM 128
#define CCH 16
#define FOUT 32
#define KK 5
#define HO 124
#define WO 124
#define NP (4 * HO * WO)     // 61504 = 961 * 64
#define HW (HO * WO)

__device__ float4 g_tw[25 * NP];      // [j][P] bilinear weights
__device__ uint4  g_toff[25 * NP];    // [j][P] tap byte offsets
__device__ uint4  g_bfrag[25 * 4 * 32];

__device__ __forceinline__ uint32_t f2tf32(float x) {
    uint32_t r;
    asm("cvt.rn.tf32.f32 %0, %1;" : "=r"(r) : "f"(x));
    return r;
}

__device__ __forceinline__ void mma_tf32(float* c,
                                         uint32_t a0, uint32_t a1,
                                         uint32_t a2, uint32_t a3,
                                         uint32_t b0, uint32_t b1) {
    asm volatile(
        "mma.sync.aligned.m16n8k8.row.col.f32.tf32.tf32.f32 "
        "{%0,%1,%2,%3}, {%4,%5,%6,%7}, {%8,%9}, {%0,%1,%2,%3};"
        : "+f"(c[0]), "+f"(c[1]), "+f"(c[2]), "+f"(c[3])
        : "r"(a0), "r"(a1), "r"(a2), "r"(a3), "r"(b0), "r"(b1));
}

// ---------------- A: angles + tap records (+ W fragments, block 0) ----------------
__global__ void __launch_bounds__(256)
rot_prep_kernel(const float* __restrict__ in, const float* __restrict__ Wg)
{
    const int tid = threadIdx.x;
    const int pp  = tid >> 2;
    const int g   = tid & 3;
    const int P   = blockIdx.x * 64 + pp;

    const int b   = P / HW;
    const int rem = P - b * HW;
    const int ho  = rem / WO;
    const int wo  = rem - ho * WO;
    const float* pb = in + ((b * HDIM + ho) * HDIM + wo) * CCH + g * 4;

    float tot = 0.f, sr = 0.f, sc = 0.f;
    #pragma unroll
    for (int r = 0; r < KK; r++) {
        #pragma unroll
        for (int cl = 0; cl < KK; cl++) {
            float4 v = *reinterpret_cast<const float4*>(pb + (r * HDIM + cl) * CCH);
            float s = v.x + v.y + v.z + v.w;
            tot += s;
            sr  += s * (float)r;
            sc  += s * (float)cl;
        }
    }
    tot += __shfl_xor_sync(0xffffffffu, tot, 1);
    tot += __shfl_xor_sync(0xffffffffu, tot, 2);
    sr  += __shfl_xor_sync(0xffffffffu, sr, 1);
    sr  += __shfl_xor_sync(0xffffffffu, sr, 2);
    sc  += __shfl_xor_sync(0xffffffffu, sc, 1);
    sc  += __shfl_xor_sync(0xffffffffu, sc, 2);

    tot += 1e-7f;
    const float cr   = sr / tot;
    const float ccen = sc / tot;
    const float m    = (float)(KK - 1) * 0.5f;
    const float ang  = atan2f(cr - m, ccen - m + 1e-7f);
    const float co   = __cosf(ang);
    const float si   = __sinf(ang);
    const float km1  = (float)(KK - 1);
    const float xo   = (km1 - (co * km1 - si * km1)) * 0.5f;
    const float yo   = (km1 - (si * km1 + co * km1)) * 0.5f;
    const float scale = 1.0f / (1.0f + 1e-7f);

    // this lane generates tap records for j = g, g+4, ...
    for (int j = g; j < 25; j += 4) {
        const int jy = j / KK;
        const int jx = j - jy * KK;
        const float sx  = (co * (float)jx - si * (float)jy + xo) * scale;
        const float sy  = (si * (float)jx + co * (float)jy + yo) * scale;
        const float x0f = floorf(sx);
        const float y0f = floorf(sy);
        const float wx  = sx - x0f;
        const float wy  = sy - y0f;
        const int   x0  = (int)x0f;
        const int   y0  = (int)y0f;
        const int   x1  = x0 + 1;
        const int   y1  = y0 + 1;

        const bool vx0 = (unsigned)x0 < KK;
        const bool vx1 = (unsigned)x1 < KK;
        const bool vy0 = (unsigned)y0 < KK;
        const bool vy1 = (unsigned)y1 < KK;
        const int x0c = min(max(x0, 0), KK - 1);
        const int x1c = min(max(x1, 0), KK - 1);
        const int y0c = min(max(y0, 0), KK - 1);
        const int y1c = min(max(y1, 0), KK - 1);

        const float wx1 = 1.f - wx;
        const float wy1 = 1.f - wy;
        float4 w;
        w.x = (vx0 && vy0) ? wx1 * wy1 : 0.f;
        w.y = (vx1 && vy0) ? wx  * wy1 : 0.f;
        w.z = (vx0 && vy1) ? wx1 * wy  : 0.f;
        w.w = (vx1 && vy1) ? wx  * wy  : 0.f;

        uint4 o;   // byte offsets within patch (channel 0): (y*128 + x)*16 floats *4B
        o.x = (uint32_t)((y0c * HDIM + x0c) * CCH * 4);
        o.y = (uint32_t)((y0c * HDIM + x1c) * CCH * 4);
        o.z = (uint32_t)((y1c * HDIM + x0c) * CCH * 4);
        o.w = (uint32_t)((y1c * HDIM + x1c) * CCH * 4);

        g_tw[j * NP + P]   = w;
        g_toff[j * NP + P] = o;
    }

    if (blockIdx.x == 0) {
        uint32_t* bf = reinterpret_cast<uint32_t*>(g_bfrag);
        for (int k = tid; k < 25 * 4 * 32 * 4; k += 256) {
            const int r2  = k & 3;
            const int ln  = (k >> 2) & 31;
            const int ntp = (k >> 7) & 1;
            const int ks  = (k >> 8) & 1;
            const int j   = k >> 9;
            const int nt  = 2 * ntp + (r2 >> 1);
            const int r   = r2 & 1;
            bf[k] = f2tf32(Wg[(nt * 8 + (ln >> 2)) * 400 + j * 16 + 4 * (ln & 3) + 2 * ks + r]);
        }
    }
}

// ---------------- B: record-driven taps + mma ----------------
__global__ void __launch_bounds__(128, 6)
rotconv13_kernel(const float* __restrict__ in,
                 const float* __restrict__ bias,
                 float* __restrict__ out)
{
    const int tid  = threadIdx.x;
    const int wid  = tid >> 5;
    const int lane = tid & 31;
    const int q    = lane & 3;
    const int row  = lane >> 2;
    const int tb   = blockIdx.x * 64 + wid * 16;   // exact grid

    const char*   pbch[2];
    const float4* rw[2];
    const uint4*  ro[2];
    #pragma unroll
    for (int u = 0; u < 2; u++) {
        const int P   = tb + row + 8 * u;
        const int b   = P / HW;
        const int rem = P - b * HW;
        const int ho  = rem / WO;
        const int wo  = rem - ho * WO;
        pbch[u] = reinterpret_cast<const char*>(
            in + ((b * HDIM + ho) * HDIM + wo) * CCH + q * 4);
        rw[u] = g_tw + P;
        ro[u] = g_toff + P;
    }

    float acc[4][4];
    #pragma unroll
    for (int nt = 0; nt < 4; nt++)
        #pragma unroll
        for (int k = 0; k < 4; k++) acc[nt][k] = 0.f;

    #pragma unroll 1
    for (int j = 0; j < 25; j++) {
        const uint4* bp = g_bfrag + j * 4 * 32 + lane;
        const uint4 bk0a = __ldg(bp);
        const uint4 bk0b = __ldg(bp + 32);
        const uint4 bk1a = __ldg(bp + 64);
        const uint4 bk1b = __ldg(bp + 96);

        uint32_t ra[2][4];
        #pragma unroll
        for (int u = 0; u < 2; u++) {
            const float4 w = __ldg(rw[u]);
            const uint4  o = __ldg(ro[u]);
            rw[u] += NP;
            ro[u] += NP;

            const float4 v00 = *reinterpret_cast<const float4*>(pbch[u] + o.x);
            const float4 v01 = *reinterpret_cast<const float4*>(pbch[u] + o.y);
            const float4 v10 = *reinterpret_cast<const float4*>(pbch[u] + o.z);
            const float4 v11 = *reinterpret_cast<const float4*>(pbch[u] + o.w);

            ra[u][0] = f2tf32(w.x * v00.x + w.y * v01.x + w.z * v10.x + w.w * v11.x);
            ra[u][1] = f2tf32(w.x * v00.y + w.y * v01.y + w.z * v10.y + w.w * v11.y);
            ra[u][2] = f2tf32(w.x * v00.z + w.y * v01.z + w.z * v10.z + w.w * v11.z);
            ra[u][3] = f2tf32(w.x * v00.w + w.y * v01.w + w.z * v10.w + w.w * v11.w);
        }

        mma_tf32(acc[0], ra[0][0], ra[1][0], ra[0][1], ra[1][1], bk0a.x, bk0a.y);
        mma_tf32(acc[1], ra[0][0], ra[1][0], ra[0][1], ra[1][1], bk0a.z, bk0a.w);
        mma_tf32(acc[2], ra[0][0], ra[1][0], ra[0][1], ra[1][1], bk0b.x, bk0b.y);
        mma_tf32(acc[3], ra[0][0], ra[1][0], ra[0][1], ra[1][1], bk0b.z, bk0b.w);
        mma_tf32(acc[0], ra[0][2], ra[1][2], ra[0][3], ra[1][3], bk1a.x, bk1a.y);
        mma_tf32(acc[1], ra[0][2], ra[1][2], ra[0][3], ra[1][3], bk1a.z, bk1a.w);
        mma_tf32(acc[2], ra[0][2], ra[1][2], ra[0][3], ra[1][3], bk1b.x, bk1b.y);
        mma_tf32(acc[3], ra[0][2], ra[1][2], ra[0][3], ra[1][3], bk1b.z, bk1b.w);
    }

    #pragma unroll
    for (int nt = 0; nt < 4; nt++) {
        const float2 bv = *reinterpret_cast<const float2*>(bias + nt * 8 + 2 * q);
        float* o0 = out + (tb + row) * FOUT + nt * 8 + 2 * q;
        float* o1 = out + (tb + row + 8) * FOUT + nt * 8 + 2 * q;
        float2 v0, v1;
        v0.x = acc[nt][0] + bv.x;  v0.y = acc[nt][1] + bv.y;
        v1.x = acc[nt][2] + bv.x;  v1.y = acc[nt][3] + bv.y;
        *reinterpret_cast<float2*>(o0) = v0;
        *reinterpret_cast<float2*>(o1) = v1;
    }
}

extern "C" void kernel_launch(void* const* d_in, const int* in_sizes, int n_in,
                              void* d_out, int out_size)
{
    const float* in   = (const float*)d_in[0];   // [4,128,128,16]
    const float* Wg   = (const float*)d_in[1];   // [32,5,5,16]
    const float* bias = (const float*)d_in[2];   // [32]
    float* out = (float*)d_out;                  // [4,124,124,32]

    rot_prep_kernel<<<NP / 64, 256>>>(in, Wg);            // 961 blocks
    rotconv13_kernel<<<NP / 64, 128>>>(in, bias, out);    // 961 blocks
}

// round 14
// speedup vs baseline: 1.6796x; 1.6796x over previous
#include <cuda_runtime.h>
#include <cuda_bf16.h>
#include <math.h>
#include <cstdint>

// RotationalConv2D v14 — GB300 sm_103a — v11 + unrolled inner jx loop (ILP)
// Kernel A: per-patch angle float4 (scale-folded) + tf32 B-fragment table.
// Kernel B: smem-free tf32 mma.sync main kernel; jy loop rolled, jx loop
//           fully unrolled so ptxas overlaps 5 independent tap/coord chains.

#define HDIM 128
#define CCH 16
#define FOUT 32
#define KK 5
#define HO 124
#define WO 124
#define NP (4 * HO * WO)     // 61504 = 961 * 64
#define HW (HO * WO)

__device__ float4 g_ang[NP];              // (co*s, si*s, xo*s, yo*s)
__device__ uint4  g_bfrag[25 * 4 * 32];   // [j][slot][lane]

__device__ __forceinline__ uint32_t f2tf32(float x) {
    uint32_t r;
    asm("cvt.rn.tf32.f32 %0, %1;" : "=r"(r) : "f"(x));
    return r;
}

__device__ __forceinline__ void mma_tf32(float* c,
                                         uint32_t a0, uint32_t a1,
                                         uint32_t a2, uint32_t a3,
                                         uint32_t b0, uint32_t b1) {
    asm volatile(
        "mma.sync.aligned.m16n8k8.row.col.f32.tf32.tf32.f32 "
        "{%0,%1,%2,%3}, {%4,%5,%6,%7}, {%8,%9}, {%0,%1,%2,%3};"
        : "+f"(c[0]), "+f"(c[1]), "+f"(c[2]), "+f"(c[3])
        : "r"(a0), "r"(a1), "r"(a2), "r"(a3), "r"(b0), "r"(b1));
}

// ---------------- Kernel A: angles (+ W fragments from block 0) ----------------
__global__ void __launch_bounds__(256)
rot_angles_kernel(const float* __restrict__ in, const float* __restrict__ Wg)
{
    const int tid = threadIdx.x;
    const int pp  = tid >> 2;
    const int g   = tid & 3;
    const int P   = blockIdx.x * 64 + pp;

    const int b   = P / HW;
    const int rem = P - b * HW;
    const int ho  = rem / WO;
    const int wo  = rem - ho * WO;
    const float* pb = in + ((b * HDIM + ho) * HDIM + wo) * CCH + g * 4;

    float tot = 0.f, sr = 0.f, sc = 0.f;
    #pragma unroll
    for (int r = 0; r < KK; r++) {
        #pragma unroll
        for (int cl = 0; cl < KK; cl++) {
            float4 v = *reinterpret_cast<const float4*>(pb + (r * HDIM + cl) * CCH);
            float s = v.x + v.y + v.z + v.w;
            tot += s;
            sr  += s * (float)r;
            sc  += s * (float)cl;
        }
    }
    tot += __shfl_xor_sync(0xffffffffu, tot, 1);
    tot += __shfl_xor_sync(0xffffffffu, tot, 2);
    sr  += __shfl_xor_sync(0xffffffffu, sr, 1);
    sr  += __shfl_xor_sync(0xffffffffu, sr, 2);
    sc  += __shfl_xor_sync(0xffffffffu, sc, 1);
    sc  += __shfl_xor_sync(0xffffffffu, sc, 2);

    if (g == 0) {
        tot += 1e-7f;
        const float cr   = sr / tot;
        const float ccen = sc / tot;
        const float m    = (float)(KK - 1) * 0.5f;
        const float ang  = atan2f(cr - m, ccen - m + 1e-7f);
        const float co   = __cosf(ang);
        const float si   = __sinf(ang);
        const float km1  = (float)(KK - 1);
        const float scale = 1.0f / (1.0f + 1e-7f);
        g_ang[P] = make_float4(co * scale, si * scale,
                               (km1 - (co * km1 - si * km1)) * 0.5f * scale,
                               (km1 - (si * km1 + co * km1)) * 0.5f * scale);
    }

    if (blockIdx.x == 0) {
        uint32_t* bf = reinterpret_cast<uint32_t*>(g_bfrag);
        for (int i = tid; i < 25 * 4 * 32 * 4; i += 256) {
            const int r2  = i & 3;
            const int ln  = (i >> 2) & 31;
            const int ntp = (i >> 7) & 1;
            const int ks  = (i >> 8) & 1;
            const int j   = i >> 9;
            const int nt  = 2 * ntp + (r2 >> 1);
            const int r   = r2 & 1;
            bf[i] = f2tf32(Wg[(nt * 8 + (ln >> 2)) * 400 + j * 16 + 4 * (ln & 3) + 2 * ks + r]);
        }
    }
}

// ---------------- Kernel B: main taps + mma ----------------
__global__ void __launch_bounds__(128, 5)
rotconv14_kernel(const float* __restrict__ in,
                 const float* __restrict__ bias,
                 float* __restrict__ out)
{
    const int tid  = threadIdx.x;
    const int wid  = tid >> 5;
    const int lane = tid & 31;
    const int q    = lane & 3;
    const int row  = lane >> 2;
    const int tb   = blockIdx.x * 64 + wid * 16;   // exact grid

    float co[2], si[2], xo[2], yo[2];
    const float* pbase[2];
    #pragma unroll
    for (int u = 0; u < 2; u++) {
        const int P   = tb + row + 8 * u;
        const float4 a = g_ang[P];
        co[u] = a.x; si[u] = a.y; xo[u] = a.z; yo[u] = a.w;
        const int b   = P / HW;
        const int rem = P - b * HW;
        const int ho  = rem / WO;
        const int wo  = rem - ho * WO;
        pbase[u] = in + ((b * HDIM + ho) * HDIM + wo) * CCH + q * 4;
    }

    float acc[4][4];
    #pragma unroll
    for (int nt = 0; nt < 4; nt++)
        #pragma unroll
        for (int k = 0; k < 4; k++) acc[nt][k] = 0.f;

    #pragma unroll 1
    for (int jy = 0; jy < KK; jy++) {
        const float gy = (float)jy;
        float Ax[2], By[2];
        #pragma unroll
        for (int u = 0; u < 2; u++) {
            Ax[u] = xo[u] - si[u] * gy;    // sx = co*gx + Ax
            By[u] = yo[u] + co[u] * gy;    // sy = si*gx + By
        }
        #pragma unroll
        for (int jx = 0; jx < KK; jx++) {
            const int   j  = jy * KK + jx;
            const float gx = (float)jx;

            const uint4* bp = g_bfrag + j * 4 * 32 + lane;
            const uint4 bk0a = __ldg(bp);
            const uint4 bk0b = __ldg(bp + 32);
            const uint4 bk1a = __ldg(bp + 64);
            const uint4 bk1b = __ldg(bp + 96);

            uint32_t ra[2][4];
            #pragma unroll
            for (int u = 0; u < 2; u++) {
                const float sx  = co[u] * gx + Ax[u];
                const float sy  = si[u] * gx + By[u];
                const float x0f = floorf(sx);
                const float y0f = floorf(sy);
                const float wx  = sx - x0f;
                const float wy  = sy - y0f;
                const int   x0  = (int)x0f;
                const int   y0  = (int)y0f;
                const int   x1  = x0 + 1;
                const int   y1  = y0 + 1;

                const bool vx0 = (unsigned)x0 < KK;
                const bool vx1 = (unsigned)x1 < KK;
                const bool vy0 = (unsigned)y0 < KK;
                const bool vy1 = (unsigned)y1 < KK;
                const int x0c = min(max(x0, 0), KK - 1);
                const int x1c = min(max(x1, 0), KK - 1);
                const int y0c = min(max(y0, 0), KK - 1);
                const int y1c = min(max(y1, 0), KK - 1);

                const float wx1 = 1.f - wx;
                const float wy1 = 1.f - wy;
                const float w00 = (vx0 && vy0) ? wx1 * wy1 : 0.f;
                const float w01 = (vx1 && vy0) ? wx  * wy1 : 0.f;
                const float w10 = (vx0 && vy1) ? wx1 * wy  : 0.f;
                const float w11 = (vx1 && vy1) ? wx  * wy  : 0.f;

                const float* r0 = pbase[u] + y0c * (HDIM * CCH);
                const float* r1 = pbase[u] + y1c * (HDIM * CCH);
                const float4 v00 = *reinterpret_cast<const float4*>(r0 + x0c * CCH);
                const float4 v01 = *reinterpret_cast<const float4*>(r0 + x1c * CCH);
                const float4 v10 = *reinterpret_cast<const float4*>(r1 + x0c * CCH);
                const float4 v11 = *reinterpret_cast<const float4*>(r1 + x1c * CCH);

                ra[u][0] = f2tf32(w00 * v00.x + w01 * v01.x + w10 * v10.x + w11 * v11.x);
                ra[u][1] = f2tf32(w00 * v00.y + w01 * v01.y + w10 * v10.y + w11 * v11.y);
                ra[u][2] = f2tf32(w00 * v00.z + w01 * v01.z + w10 * v10.z + w11 * v11.z);
                ra[u][3] = f2tf32(w00 * v00.w + w01 * v01.w + w10 * v10.w + w11 * v11.w);
            }

            mma_tf32(acc[0], ra[0][0], ra[1][0], ra[0][1], ra[1][1], bk0a.x, bk0a.y);
            mma_tf32(acc[1], ra[0][0], ra[1][0], ra[0][1], ra[1][1], bk0a.z, bk0a.w);
            mma_tf32(acc[2], ra[0][0], ra[1][0], ra[0][1], ra[1][1], bk0b.x, bk0b.y);
            mma_tf32(acc[3], ra[0][0], ra[1][0], ra[0][1], ra[1][1], bk0b.z, bk0b.w);
            mma_tf32(acc[0], ra[0][2], ra[1][2], ra[0][3], ra[1][3], bk1a.x, bk1a.y);
            mma_tf32(acc[1], ra[0][2], ra[1][2], ra[0][3], ra[1][3], bk1a.z, bk1a.w);
            mma_tf32(acc[2], ra[0][2], ra[1][2], ra[0][3], ra[1][3], bk1b.x, bk1b.y);
            mma_tf32(acc[3], ra[0][2], ra[1][2], ra[0][3], ra[1][3], bk1b.z, bk1b.w);
        }
    }

    #pragma unroll
    for (int nt = 0; nt < 4; nt++) {
        const float2 bv = *reinterpret_cast<const float2*>(bias + nt * 8 + 2 * q);
        float* o0 = out + (tb + row) * FOUT + nt * 8 + 2 * q;
        float* o1 = out + (tb + row + 8) * FOUT + nt * 8 + 2 * q;
        float2 v0, v1;
        v0.x = acc[nt][0] + bv.x;  v0.y = acc[nt][1] + bv.y;
        v1.x = acc[nt][2] + bv.x;  v1.y = acc[nt][3] + bv.y;
        *reinterpret_cast<float2*>(o0) = v0;
        *reinterpret_cast<float2*>(o1) = v1;
    }
}

extern "C" void kernel_launch(void* const* d_in, const int* in_sizes, int n_in,
                              void* d_out, int out_size)
{
    const float* in   = (const float*)d_in[0];   // [4,128,128,16]
    const float* Wg   = (const float*)d_in[1];   // [32,5,5,16]
    const float* bias = (const float*)d_in[2];   // [32]
    float* out = (float*)d_out;                  // [4,124,124,32]

    rot_angles_kernel<<<NP / 64, 256>>>(in, Wg);          // 961 blocks
    rotconv14_kernel<<<NP / 64, 128>>>(in, bias, out);    // 961 blocks
}